// round 11
// baseline (speedup 1.0000x reference)
#include <cuda_runtime.h>
#include <math.h>
#include <stdint.h>

// ====================================================================
// Static device scratch
// ====================================================================
__device__ __align__(256) float g_knT[128 * 800];
__device__ __align__(256) float g_hnT[128 * 800];
__device__ __align__(256) float g_A  [16 * 32 * 128 * 128];   // center enc1 out
__device__ __align__(256) float g_A2 [16 * 16 * 128 * 128];   // skip enc1 out
__device__ __align__(256) float g_zc [16 * 128 * 64 * 64];
__device__ __align__(256) float g_zs [16 * 128 * 64 * 64];
__device__ __align__(256) float g_Sact[16 * 384 * 800];
__device__ __align__(256) int   g_tidx[16 * 324 * 10];
__device__ __align__(256) float g_tw  [16 * 324 * 10];
__device__ __align__(256) int   g_amax[65536];
__device__ __align__(256) float g_pv  [7 * 65536];
__device__ __align__(256) int   g_pi  [7 * 65536];
__device__ __align__(256) float g_bgz [128];
__device__ __align__(256) float g_c9  [64 * 9];
__device__ __align__(256) float g_gdelta[16 * 128 * 324];
__device__ __align__(256) float g_zmS[16 * 128 * 64 * 64];    // skip gather only
__device__ __align__(256) float g_d1 [16 * 64 * 64 * 64];     // raw (pre-relu)
__device__ __align__(256) float g_u1 [16 * 32 * 128 * 128];
__device__ __align__(256) float g_u2 [16 * 16 * 256 * 256];

// ====================================================================
// Normalize memory rows -> transposed tables knT[c][m], hnT[c][m]
// ====================================================================
__global__ void k_normrows(const float* __restrict__ keys,
                           const float* __restrict__ hard,
                           float* __restrict__ knT, float* __restrict__ hnT)
{
    int gw = (blockIdx.x * blockDim.x + threadIdx.x) >> 5;
    int lane = threadIdx.x & 31;
    if (gw >= 1600) return;
    const float* src; float* dst; int r;
    if (gw < 800) { src = keys; dst = knT; r = gw; }
    else          { src = hard; dst = hnT; r = gw - 800; }
    float4 v = *(const float4*)(src + (size_t)r * 128 + lane * 4);
    float s = v.x * v.x + v.y * v.y + v.z * v.z + v.w * v.w;
#pragma unroll
    for (int o = 16; o > 0; o >>= 1) s += __shfl_xor_sync(0xffffffffu, s, o);
    float d = 1.0f / fmaxf(sqrtf(s), 1e-12f);
    dst[(size_t)(4 * lane + 0) * 800 + r] = v.x * d;
    dst[(size_t)(4 * lane + 1) * 800 + r] = v.y * d;
    dst[(size_t)(4 * lane + 2) * 800 + r] = v.z * d;
    dst[(size_t)(4 * lane + 3) * 800 + r] = v.w * d;
}

// ====================================================================
// Background z_match: bgc -> scores -> topk -> softmax -> gather (1 block)
// ====================================================================
__global__ __launch_bounds__(256) void k_bg(const float* __restrict__ w2,
    const float* __restrict__ b1, const float* __restrict__ b2,
    const float* __restrict__ knT, const float* __restrict__ vals,
    float* __restrict__ bgz)
{
    __shared__ float bgc[128];
    __shared__ float sc[800];
    __shared__ int   swidx[10];
    __shared__ float sww[10];
    const int tid = threadIdx.x;
    if (tid < 128) {
        float s = b2[tid];
        for (int ic = 0; ic < 32; ic++) {
            float wsum = 0.f;
#pragma unroll
            for (int k = 0; k < 9; k++) wsum += w2[((size_t)tid * 32 + ic) * 9 + k];
            s = fmaf(wsum, fmaxf(b1[ic], 0.f), s);
        }
        bgc[tid] = fmaxf(s, 0.f);
    }
    __syncthreads();
    for (int m = tid; m < 800; m += 256) {
        float s = 0.f;
#pragma unroll 8
        for (int c = 0; c < 128; c++) s = fmaf(bgc[c], knT[(size_t)c * 800 + m], s);
        sc[m] = s;
    }
    __syncthreads();
    if (tid < 32) {
        const int lane = tid;
        float ss = 0.f;
#pragma unroll
        for (int j = 0; j < 4; j++) { float v = bgc[lane * 4 + j]; ss = fmaf(v, v, ss); }
#pragma unroll
        for (int o = 16; o > 0; o >>= 1) ss += __shfl_xor_sync(0xffffffffu, ss, o);
        float scale = 1.0f / fmaxf(sqrtf(ss), 1e-12f);
        float lv[10]; int li[10];
#pragma unroll
        for (int j = 0; j < 10; j++) { lv[j] = -INFINITY; li[j] = 0x7fffffff; }
        for (int t = 0; t < 25; t++) {
            int m = lane + 32 * t;
            float v = sc[m];
            int i = m;
#pragma unroll
            for (int j = 0; j < 10; j++) {
                bool better = (v > lv[j]) || (v == lv[j] && i < li[j]);
                if (better) {
                    float tv = lv[j]; lv[j] = v; v = tv;
                    int ti = li[j]; li[j] = i; i = ti;
                }
            }
        }
        float bv[10]; int bi[10];
#pragma unroll
        for (int k = 0; k < 10; k++) {
            float cv = lv[0]; int ci = li[0];
#pragma unroll
            for (int off = 16; off > 0; off >>= 1) {
                float ov = __shfl_xor_sync(0xffffffffu, cv, off);
                int   oi = __shfl_xor_sync(0xffffffffu, ci, off);
                if (ov > cv || (ov == cv && oi < ci)) { cv = ov; ci = oi; }
            }
            bv[k] = cv; bi[k] = ci;
            if (lv[0] == cv && li[0] == ci) {
#pragma unroll
                for (int j = 0; j < 9; j++) { lv[j] = lv[j + 1]; li[j] = li[j + 1]; }
                lv[9] = -INFINITY; li[9] = 0x7fffffff;
            }
        }
        if (lane == 0) {
            float mx = bv[0] * scale;
            float e[10], sum = 0.f;
#pragma unroll
            for (int k = 0; k < 10; k++) { e[k] = expf(bv[k] * scale - mx); sum += e[k]; }
            float inv = 1.0f / sum;
#pragma unroll
            for (int k = 0; k < 10; k++) { swidx[k] = bi[k]; sww[k] = e[k] * inv; }
        }
    }
    __syncthreads();
    if (tid < 128) {
        float a = 0.f;
#pragma unroll
        for (int k = 0; k < 10; k++)
            a = fmaf(vals[(size_t)swidx[k] * 128 + tid], sww[k], a);
        bgz[tid] = a;
    }
}

// ====================================================================
// C9 prep: c9[oc][cy][cx] = dec_b1[oc] + sum_ic<128 bgz[ic]*sum_{valid taps} w1
// ====================================================================
__global__ void k_prepC9(const float* __restrict__ w, const float* __restrict__ bias,
                         const float* __restrict__ bgz, float* __restrict__ c9)
{
    for (int idx = threadIdx.x; idx < 576; idx += 256) {
        int oc = idx / 9, cs = idx % 9, cy = cs / 3, cx = cs % 3;
        int dy0 = (cy == 0) ? 1 : 0, dy1 = (cy == 2) ? 1 : 2;
        int dx0 = (cx == 0) ? 1 : 0, dx1 = (cx == 2) ? 1 : 2;
        float s = bias[oc];
        for (int ic = 0; ic < 128; ic++) {
            float t = 0.f;
            const float* wp = w + ((size_t)oc * 256 + ic) * 9;
            for (int dy = dy0; dy <= dy1; dy++)
                for (int dx = dx0; dx <= dx1; dx++)
                    t += wp[dy * 3 + dx];
            s = fmaf(bgz[ic], t, s);
        }
        c9[idx] = s;
    }
}

// ====================================================================
// Fill A (enc1-center out) with relu(b1[c])
// ====================================================================
__global__ void k_fillA(float* __restrict__ A, const float* __restrict__ b1)
{
    int i = blockIdx.x * blockDim.x + threadIdx.x;   // < 16*32*16384
    int c = (i >> 14) & 31;
    A[i] = fmaxf(b1[c], 0.f);
}

// ====================================================================
// Encoder stage 1: conv3x3 (1 -> CO) + relu + maxpool2, tile offset.
// ====================================================================
template<int CO, bool MASK>
__global__ __launch_bounds__(256) void k_enc1(const float* __restrict__ x,
    const float* __restrict__ w, const float* __restrict__ bias,
    float* __restrict__ out, int offX, int offY)
{
    __shared__ float tile[34][36];
    __shared__ float sw[CO * 9];
    __shared__ float sb[CO];
    const int t  = threadIdx.x;
    const int b  = blockIdx.z;
    const int Y0 = (blockIdx.y + offY) * 32;
    const int X0 = (blockIdx.x + offX) * 32;
    const float* xb = x + (size_t)b * 65536;
    for (int i = t; i < 34 * 34; i += 256) {
        int r = i / 34, c = i % 34;
        int gy = Y0 + r - 1, gx = X0 + c - 1;
        bool ok = (gy >= 0 && gy < 256 && gx >= 0 && gx < 256);
        if (MASK) ok = ok && (gy >= 96 && gy < 160 && gx >= 96 && gx < 160);
        tile[r][c] = ok ? xb[gy * 256 + gx] : 0.f;
    }
    for (int i = t; i < CO * 9; i += 256) sw[i] = w[i];
    if (t < CO) sb[t] = bias[t];
    __syncthreads();
    const int ty = t >> 4, tx = t & 15;
    float p[4][4];
#pragma unroll
    for (int i = 0; i < 4; i++)
#pragma unroll
        for (int j = 0; j < 4; j++) p[i][j] = tile[2 * ty + i][2 * tx + j];
    const int py = (blockIdx.y + offY) * 16 + ty, px = (blockIdx.x + offX) * 16 + tx;
    float* ob = out + (size_t)b * CO * 128 * 128 + py * 128 + px;
#pragma unroll 4
    for (int oc = 0; oc < CO; oc++) {
        float w9[9];
#pragma unroll
        for (int k = 0; k < 9; k++) w9[k] = sw[oc * 9 + k];
        float bv = sb[oc];
        float m = -INFINITY;
#pragma unroll
        for (int i = 0; i < 2; i++)
#pragma unroll
            for (int j = 0; j < 2; j++) {
                float s = bv;
#pragma unroll
                for (int dy = 0; dy < 3; dy++)
#pragma unroll
                    for (int dx = 0; dx < 3; dx++)
                        s = fmaf(w9[dy * 3 + dx], p[i + dy][j + dx], s);
                m = fmaxf(m, fmaxf(s, 0.f));
            }
        ob[(size_t)oc * 128 * 128] = m;
    }
}

// ====================================================================
// conv3x3 pad1. 64(w) x 32(h) output tile, 128 threads, 4x4 px/thread.
// ICw = weight oc-stride; C9MODE adds c9[oc][case] (bias folded).
// ====================================================================
template<int OCB, bool RELU, bool POOL, bool C9MODE>
__global__ __launch_bounds__(128) void k_conv3c(const float* __restrict__ in,
    const float* __restrict__ w, const float* __restrict__ bias,
    float* __restrict__ out, int IC, int ICw, int OC, int H, int W, int tilesY,
    int offXpx, int offYpx, const float* __restrict__ c9)
{
    __shared__ float tin[4][34][66];
    __shared__ float sw[OCB][4][9];
    const int tY = blockIdx.y % tilesY;
    const int ob = blockIdx.y / tilesY;
    const int Y0 = tY * 32 + offYpx;
    const int X0 = blockIdx.x * 64 + offXpx;
    const int b  = blockIdx.z;
    const int tid = threadIdx.x;
    const int ty = tid >> 4;
    const int tx = tid & 15;
    float acc[OCB][4][4];
#pragma unroll
    for (int o = 0; o < OCB; o++)
#pragma unroll
        for (int e = 0; e < 4; e++)
#pragma unroll
            for (int f = 0; f < 4; f++) acc[o][e][f] = 0.f;
    const float* inb = in + (size_t)b * IC * H * W;
    for (int ic0 = 0; ic0 < IC; ic0 += 4) {
        __syncthreads();
        for (int i = tid; i < 4 * 34 * 66; i += 128) {
            int ic = i / (34 * 66); int rem = i % (34 * 66);
            int r = rem / 66, c = rem % 66;
            int gy = Y0 + r - 1, gx = X0 + c - 1;
            float v = 0.f;
            if (gy >= 0 && gy < H && gx >= 0 && gx < W)
                v = inb[(size_t)(ic0 + ic) * H * W + gy * W + gx];
            tin[ic][r][c] = v;
        }
        for (int i = tid; i < OCB * 4 * 9; i += 128) {
            int o = i / 36; int rem = i % 36; int ic = rem / 9; int k = rem % 9;
            sw[o][ic][k] = w[((size_t)(ob * OCB + o) * ICw + ic0 + ic) * 9 + k];
        }
        __syncthreads();
#pragma unroll
        for (int ic = 0; ic < 4; ic++) {
            float p[6][6];
#pragma unroll
            for (int i = 0; i < 6; i++)
#pragma unroll
                for (int j = 0; j < 6; j++)
                    p[i][j] = tin[ic][4 * ty + i][4 * tx + j];
#pragma unroll
            for (int o = 0; o < OCB; o++) {
                float w9[9];
#pragma unroll
                for (int k = 0; k < 9; k++) w9[k] = sw[o][ic][k];
#pragma unroll
                for (int e = 0; e < 4; e++)
#pragma unroll
                    for (int f = 0; f < 4; f++) {
                        float s = acc[o][e][f];
#pragma unroll
                        for (int dy = 0; dy < 3; dy++)
#pragma unroll
                            for (int dx = 0; dx < 3; dx++)
                                s = fmaf(w9[dy * 3 + dx], p[e + dy][f + dx], s);
                        acc[o][e][f] = s;
                    }
            }
        }
    }
#pragma unroll
    for (int o = 0; o < OCB; o++) {
        int oc = ob * OCB + o;
        if (C9MODE) {
#pragma unroll
            for (int e = 0; e < 4; e++) {
                int gy = Y0 + 4 * ty + e;
                int cyi = (gy == 0) ? 0 : ((gy == H - 1) ? 6 : 3);
                float vv[4];
#pragma unroll
                for (int f = 0; f < 4; f++) {
                    int gx = X0 + 4 * tx + f;
                    int cxi = (gx == 0) ? 0 : ((gx == W - 1) ? 2 : 1);
                    vv[f] = acc[o][e][f] + c9[oc * 9 + cyi + cxi];
                }
                *(float4*)(out + ((size_t)((size_t)b * OC + oc) * H + gy) * W
                               + X0 + 4 * tx) = make_float4(vv[0], vv[1], vv[2], vv[3]);
            }
        } else {
            float bv = bias[oc];
            if (POOL) {
                int Ho = H >> 1, Wo = W >> 1;
#pragma unroll
                for (int e = 0; e < 2; e++)
#pragma unroll
                    for (int f = 0; f < 2; f++) {
                        float m = -INFINITY;
#pragma unroll
                        for (int r = 0; r < 2; r++)
#pragma unroll
                            for (int c = 0; c < 2; c++)
                                m = fmaxf(m, fmaxf(acc[o][2 * e + r][2 * f + c] + bv, 0.f));
                        out[((size_t)((size_t)b * OC + oc) * Ho + ((Y0 >> 1) + 2 * ty + e)) * Wo
                            + (X0 >> 1) + 2 * tx + f] = m;
                    }
            } else {
#pragma unroll
                for (int e = 0; e < 4; e++) {
                    float v0 = acc[o][e][0] + bv, v1 = acc[o][e][1] + bv;
                    float v2 = acc[o][e][2] + bv, v3 = acc[o][e][3] + bv;
                    if (RELU) {
                        v0 = fmaxf(v0, 0.f); v1 = fmaxf(v1, 0.f);
                        v2 = fmaxf(v2, 0.f); v3 = fmaxf(v3, 0.f);
                    }
                    *(float4*)(out + ((size_t)((size_t)b * OC + oc) * H + (Y0 + 4 * ty + e)) * W
                                   + X0 + 4 * tx) = make_float4(v0, v1, v2, v3);
                }
            }
        }
    }
}

// ====================================================================
// Delta conv for dec1: d1[b][oc][y][x] += conv(gdelta) on window [22,42)^2
// ====================================================================
__global__ __launch_bounds__(256) void k_dec1delta(
    const float* __restrict__ gdelta, const float* __restrict__ w,
    float* __restrict__ d1)
{
    __shared__ float sd[16][324];
    __shared__ float sw[16][16][9];
    const int b  = blockIdx.y;
    const int og = blockIdx.x;
    const int tid = threadIdx.x;
    float acc[2][16];
#pragma unroll
    for (int pp = 0; pp < 2; pp++)
#pragma unroll
        for (int o = 0; o < 16; o++) acc[pp][o] = 0.f;
    for (int ic0 = 0; ic0 < 128; ic0 += 16) {
        __syncthreads();
        for (int i = tid; i < 16 * 324; i += 256)
            sd[i / 324][i % 324] = gdelta[((size_t)b * 128 + ic0 + i / 324) * 324 + i % 324];
        for (int i = tid; i < 16 * 16 * 9; i += 256) {
            int o = i / 144, r = i % 144, ic = r / 9, k = r % 9;
            sw[o][ic][k] = w[((size_t)(og * 16 + o) * 256 + ic0 + ic) * 9 + k];
        }
        __syncthreads();
#pragma unroll
        for (int pp = 0; pp < 2; pp++) {
            int p = pp * 256 + tid;
            if (p >= 400) continue;
            int y = 22 + p / 20, x = 22 + p % 20;
            for (int ic = 0; ic < 16; ic++) {
                float pv[9];
#pragma unroll
                for (int dy = 0; dy < 3; dy++)
#pragma unroll
                    for (int dx = 0; dx < 3; dx++) {
                        int r = y - 24 + dy, c = x - 24 + dx;
                        pv[dy * 3 + dx] = (r >= 0 && r < 18 && c >= 0 && c < 18)
                            ? sd[ic][r * 18 + c] : 0.f;
                    }
#pragma unroll
                for (int o = 0; o < 16; o++) {
                    float s = acc[pp][o];
#pragma unroll
                    for (int k = 0; k < 9; k++) s = fmaf(sw[o][ic][k], pv[k], s);
                    acc[pp][o] = s;
                }
            }
        }
    }
#pragma unroll
    for (int pp = 0; pp < 2; pp++) {
        int p = pp * 256 + tid;
        if (p >= 400) continue;
        int y = 22 + p / 20, x = 22 + p % 20;
#pragma unroll
        for (int o = 0; o < 16; o++) {
            size_t idx = ((size_t)b * 64 + og * 16 + o) * 4096 + y * 64 + x;
            d1[idx] += acc[pp][o];
        }
    }
}

// ====================================================================
// Center active GEMM: S_act[b*384+ai][m] = sum_c zc[b][c][n(ai)]*knT[c][m]
// ====================================================================
__global__ __launch_bounds__(256) void k_gemm_act(const float* __restrict__ A,
    const float* __restrict__ Bm, float* __restrict__ S)
{
    __shared__ float As[16][128];
    __shared__ float Bs[16][64];
    __shared__ int   map[128];
    const int b  = blockIdx.z;
    const int n0 = blockIdx.y * 128;
    const int m0 = blockIdx.x * 64;
    const int tid = threadIdx.x;
    const int tm = tid & 15, tn = tid >> 4;
    if (tid < 128) {
        int ai = n0 + tid;
        map[tid] = (ai < 324) ? ((23 + ai / 18) * 64 + 23 + ai % 18) : (23 * 64 + 23);
    }
    float acc[8][4];
#pragma unroll
    for (int i = 0; i < 8; i++)
#pragma unroll
        for (int j = 0; j < 4; j++) acc[i][j] = 0.f;
    const float* Ab = A + (size_t)b * 128 * 4096;
    const int lkB = tid >> 4, lmB = (tid * 4) & 63;
    __syncthreads();
    for (int k0 = 0; k0 < 128; k0 += 16) {
        __syncthreads();
#pragma unroll
        for (int j = 0; j < 8; j++) {
            int idx = tid * 8 + j;
            int lk = idx >> 7, ln = idx & 127;
            As[lk][ln] = Ab[(size_t)(k0 + lk) * 4096 + map[ln]];
        }
        float4 bv = make_float4(0.f, 0.f, 0.f, 0.f);
        if (m0 + lmB < 800)
            bv = *(const float4*)&Bm[(size_t)(k0 + lkB) * 800 + m0 + lmB];
        *(float4*)&Bs[lkB][lmB] = bv;
        __syncthreads();
#pragma unroll
        for (int k = 0; k < 16; k++) {
            float4 a0 = *(float4*)&As[k][tn * 8];
            float4 a1 = *(float4*)&As[k][tn * 8 + 4];
            float4 bb = *(float4*)&Bs[k][tm * 4];
            float av[8] = {a0.x, a0.y, a0.z, a0.w, a1.x, a1.y, a1.z, a1.w};
#pragma unroll
            for (int i = 0; i < 8; i++) {
                acc[i][0] = fmaf(av[i], bb.x, acc[i][0]);
                acc[i][1] = fmaf(av[i], bb.y, acc[i][1]);
                acc[i][2] = fmaf(av[i], bb.z, acc[i][2]);
                acc[i][3] = fmaf(av[i], bb.w, acc[i][3]);
            }
        }
    }
    const int m = m0 + tm * 4;
    if (m < 800) {
#pragma unroll
        for (int i = 0; i < 8; i++) {
            size_t row = (size_t)b * 384 + n0 + tn * 8 + i;
            *(float4*)&S[row * 800 + m] =
                make_float4(acc[i][0], acc[i][1], acc[i][2], acc[i][3]);
        }
    }
}

// ====================================================================
// Active top-10 + softmax (scale inline from zc). 5184 warps.
// ====================================================================
__global__ void k_topk_act(const float* __restrict__ S, const float* __restrict__ zc,
                           int* __restrict__ tidx, float* __restrict__ tw)
{
    int gw = (blockIdx.x * blockDim.x + threadIdx.x) >> 5;
    int lane = threadIdx.x & 31;
    if (gw >= 16 * 324) return;
    const int b = gw / 324, ai = gw % 324;
    const int n = (23 + ai / 18) * 64 + 23 + ai % 18;
    const float* zb = zc + (size_t)b * 128 * 4096 + n;
    float ss = 0.f;
#pragma unroll
    for (int j = 0; j < 4; j++) {
        float v = zb[(size_t)(lane + 32 * j) * 4096];
        ss = fmaf(v, v, ss);
    }
#pragma unroll
    for (int o = 16; o > 0; o >>= 1) ss += __shfl_xor_sync(0xffffffffu, ss, o);
    float sc = 1.0f / fmaxf(sqrtf(ss), 1e-12f);

    const float* row = S + ((size_t)b * 384 + ai) * 800;
    float lv[10]; int li[10];
#pragma unroll
    for (int j = 0; j < 10; j++) { lv[j] = -INFINITY; li[j] = 0x7fffffff; }
    for (int t = 0; t < 25; t++) {
        int m = lane + 32 * t;
        float v = row[m];
        int i = m;
#pragma unroll
        for (int j = 0; j < 10; j++) {
            bool better = (v > lv[j]) || (v == lv[j] && i < li[j]);
            if (better) {
                float tv = lv[j]; lv[j] = v; v = tv;
                int ti = li[j]; li[j] = i; i = ti;
            }
        }
    }
    float bv[10]; int bi[10];
#pragma unroll
    for (int k = 0; k < 10; k++) {
        float cv = lv[0]; int ci = li[0];
#pragma unroll
        for (int off = 16; off > 0; off >>= 1) {
            float ov = __shfl_xor_sync(0xffffffffu, cv, off);
            int   oi = __shfl_xor_sync(0xffffffffu, ci, off);
            if (ov > cv || (ov == cv && oi < ci)) { cv = ov; ci = oi; }
        }
        bv[k] = cv; bi[k] = ci;
        if (lv[0] == cv && li[0] == ci) {
#pragma unroll
            for (int j = 0; j < 9; j++) { lv[j] = lv[j + 1]; li[j] = li[j + 1]; }
            lv[9] = -INFINITY; li[9] = 0x7fffffff;
        }
    }
    if (lane == 0) {
        float mx = bv[0] * sc;
        float e[10], sum = 0.f;
#pragma unroll
        for (int k = 0; k < 10; k++) { e[k] = expf(bv[k] * sc - mx); sum += e[k]; }
        float inv = 1.0f / sum;
#pragma unroll
        for (int k = 0; k < 10; k++) {
            tidx[gw * 10 + k] = bi[k];
            tw[gw * 10 + k]   = e[k] * inv;
        }
    }
}

// ====================================================================
// Active weighted gather -> gdelta[b][c][ai] = z_match - bgz[c]
// ====================================================================
__global__ void k_gatherC_act(const float* __restrict__ vals, const int* __restrict__ tidx,
                              const float* __restrict__ tw, const float* __restrict__ bgz,
                              float* __restrict__ gdelta)
{
    __shared__ int   sidx[8][10];
    __shared__ float swt [8][10];
    const int r0 = blockIdx.x * 8;
    const int tid = threadIdx.x;
    if (tid < 80) {
        int ny = tid / 10, k = tid % 10;
        sidx[ny][k] = tidx[(size_t)(r0 + ny) * 10 + k];
        swt [ny][k] = tw  [(size_t)(r0 + ny) * 10 + k];
    }
    __syncthreads();
    const int cx = tid & 31, ny = tid >> 5;
    const int row = r0 + ny;
    const int b = row / 324, ai = row % 324;
#pragma unroll
    for (int cc = 0; cc < 4; cc++) {
        int c = cx + 32 * cc;
        float acc = 0.f;
#pragma unroll
        for (int k = 0; k < 10; k++)
            acc = fmaf(vals[(size_t)sidx[ny][k] * 128 + c], swt[ny][k], acc);
        gdelta[((size_t)b * 128 + c) * 324 + ai] = acc - bgz[c];
    }
}

// ====================================================================
// Skip GEMM + partial argmax over one 128-m chunk.
// grid (7 mchunks, 32 ntiles, 16 b). Writes (val, idx) partials.
// ====================================================================
__global__ __launch_bounds__(256) void k_gemm_amax_split(const float* __restrict__ A,
    const float* __restrict__ Bm, float* __restrict__ pv, int* __restrict__ pi)
{
    __shared__ float As[16][128];
    __shared__ float Bs[16][128];
    __shared__ float rv[128][17];
    __shared__ int   ri[128][17];
    const int mc = blockIdx.x;
    const int m0 = mc * 128;
    const int b  = blockIdx.z;
    const int n0 = blockIdx.y * 128;
    const int tid = threadIdx.x;
    const int tm = tid & 15, tn = tid >> 4;
    const int lk = tid >> 4, ln = (tid & 15) * 8;
    const float* Ab = A + (size_t)b * 128 * 4096;
    float acc[8][8];
#pragma unroll
    for (int i = 0; i < 8; i++)
#pragma unroll
        for (int j = 0; j < 8; j++) acc[i][j] = 0.f;
    for (int k0 = 0; k0 < 128; k0 += 16) {
        __syncthreads();
        const float* ap = &Ab[(size_t)(k0 + lk) * 4096 + n0 + ln];
        *(float4*)&As[lk][ln]     = *(const float4*)ap;
        *(float4*)&As[lk][ln + 4] = *(const float4*)(ap + 4);
        if (m0 + ln + 7 < 800) {
            const float* bp = &Bm[(size_t)(k0 + lk) * 800 + m0 + ln];
            *(float4*)&Bs[lk][ln]     = *(const float4*)bp;
            *(float4*)&Bs[lk][ln + 4] = *(const float4*)(bp + 4);
        } else {
#pragma unroll
            for (int j = 0; j < 8; j++)
                Bs[lk][ln + j] = (m0 + ln + j < 800)
                    ? Bm[(size_t)(k0 + lk) * 800 + m0 + ln + j] : 0.f;
        }
        __syncthreads();
#pragma unroll
        for (int k = 0; k < 16; k++) {
            float4 a0 = *(float4*)&As[k][tn * 8];
            float4 a1 = *(float4*)&As[k][tn * 8 + 4];
            float4 b0 = *(float4*)&Bs[k][tm * 8];
            float4 b1 = *(float4*)&Bs[k][tm * 8 + 4];
            float av[8] = {a0.x, a0.y, a0.z, a0.w, a1.x, a1.y, a1.z, a1.w};
            float bw[8] = {b0.x, b0.y, b0.z, b0.w, b1.x, b1.y, b1.z, b1.w};
#pragma unroll
            for (int i = 0; i < 8; i++)
#pragma unroll
                for (int j = 0; j < 8; j++)
                    acc[i][j] = fmaf(av[i], bw[j], acc[i][j]);
        }
    }
    float bestv[8]; int besti[8];
#pragma unroll
    for (int i = 0; i < 8; i++) { bestv[i] = -INFINITY; besti[i] = 0x7fffffff; }
#pragma unroll
    for (int i = 0; i < 8; i++)
#pragma unroll
        for (int j = 0; j < 8; j++) {
            int m = m0 + tm * 8 + j;
            float v = acc[i][j];
            if (m < 800 && (v > bestv[i] || (v == bestv[i] && m < besti[i]))) {
                bestv[i] = v; besti[i] = m;
            }
        }
    __syncthreads();
#pragma unroll
    for (int i = 0; i < 8; i++) { rv[tn * 8 + i][tm] = bestv[i]; ri[tn * 8 + i][tm] = besti[i]; }
    __syncthreads();
    if (tid < 128) {
        float bv = -INFINITY; int bi = 0x7fffffff;
#pragma unroll
        for (int t = 0; t < 16; t++) {
            float v = rv[tid][t]; int i = ri[tid][t];
            if (v > bv || (v == bv && i < bi)) { bv = v; bi = i; }
        }
        pv[(size_t)mc * 65536 + b * 4096 + n0 + tid] = bv;
        pi[(size_t)mc * 65536 + b * 4096 + n0 + tid] = bi;
    }
}

// ====================================================================
// Reduce 7 partial argmax candidates per row (ascending chunk = ascending m)
// ====================================================================
__global__ void k_amax_reduce(const float* __restrict__ pv, const int* __restrict__ pi,
                              int* __restrict__ amax)
{
    int r = blockIdx.x * 256 + threadIdx.x;
    if (r >= 65536) return;
    float bv = -INFINITY; int bi = 0x7fffffff;
#pragma unroll
    for (int c = 0; c < 7; c++) {
        float v = pv[(size_t)c * 65536 + r];
        int   i = pi[(size_t)c * 65536 + r];
        if (v > bv || (v == bv && i < bi)) { bv = v; bi = i; }
    }
    amax[r] = bi;
}

// ====================================================================
// Hard gather -> zmS[b][c][n] (128-channel layout)
// ====================================================================
__global__ void k_gatherS(const float* __restrict__ hard, const int* __restrict__ amax,
                          float* __restrict__ zmS)
{
    const int r0 = blockIdx.x * 8;
    const int tid = threadIdx.x;
    const int cx = tid & 31, ny = tid >> 5;
    const int row = r0 + ny;
    const int b = row >> 12, n = row & 4095;
    const int a = amax[row];
#pragma unroll
    for (int cc = 0; cc < 4; cc++) {
        int c = cx + 32 * cc;
        zmS[((size_t)b * 128 + c) * 4096 + n] = hard[(size_t)a * 128 + c];
    }
}

// ====================================================================
// Transposed conv (k=4, s=2) + relu out; RELUIN applies relu on input load.
// IC chunks of 4 (halved barrier count vs chunk-2).
// ====================================================================
template<int IC, int OC, int OCB, bool RELUIN>
__global__ __launch_bounds__(256) void k_deconv(const float* __restrict__ in,
    const float* __restrict__ w, const float* __restrict__ bias,
    float* __restrict__ out, int Hi, int tilesY)
{
    __shared__ float tin[4][34][36];
    __shared__ float sw[4][OCB][16];
    const int Ho = 2 * Hi;
    const int tY = blockIdx.y % tilesY;
    const int ob = blockIdx.y / tilesY;
    const int b  = blockIdx.z;
    const int Xo0 = blockIdx.x * 64, Yo0 = tY * 64;
    const int a0 = Yo0 >> 1, c0 = Xo0 >> 1;
    const int tid = threadIdx.x;
    const int ty = tid >> 4, tx = tid & 15;
    float acc[OCB][4][4];
#pragma unroll
    for (int o = 0; o < OCB; o++)
#pragma unroll
        for (int r = 0; r < 4; r++)
#pragma unroll
            for (int c = 0; c < 4; c++) acc[o][r][c] = 0.f;
    const float* inb = in + (size_t)b * IC * Hi * Hi;
    for (int ic0 = 0; ic0 < IC; ic0 += 4) {
        __syncthreads();
        for (int i = tid; i < 4 * 34 * 34; i += 256) {
            int ic = i / (34 * 34); int rem = i % (34 * 34);
            int r = rem / 34, c = rem % 34;
            int gy = a0 + r - 1, gx = c0 + c - 1;
            float v = 0.f;
            if (gy >= 0 && gy < Hi && gx >= 0 && gx < Hi) {
                v = inb[(size_t)(ic0 + ic) * Hi * Hi + gy * Hi + gx];
                if (RELUIN) v = fmaxf(v, 0.f);
            }
            tin[ic][r][c] = v;
        }
        for (int i = tid; i < 4 * OCB * 16; i += 256) {
            int ic = i / (OCB * 16); int rem = i % (OCB * 16);
            int o = rem / 16; int t = rem % 16;
            sw[ic][o][t] = w[((size_t)(ic0 + ic) * OC + ob * OCB + o) * 16 + t];
        }
        __syncthreads();
#pragma unroll
        for (int ic = 0; ic < 4; ic++) {
            float p[4][4];
#pragma unroll
            for (int i = 0; i < 4; i++)
#pragma unroll
                for (int j = 0; j < 4; j++)
                    p[i][j] = tin[ic][2 * ty + i][2 * tx + j];
#pragma unroll
            for (int o = 0; o < OCB; o++) {
                float W4[16];
#pragma unroll
                for (int t = 0; t < 16; t++) W4[t] = sw[ic][o][t];
#pragma unroll
                for (int e = 0; e < 2; e++)
#pragma unroll
                    for (int f = 0; f < 2; f++) {
                        float P00 = p[e][f],     P01 = p[e][f + 1],     P02 = p[e][f + 2];
                        float P10 = p[e + 1][f], P11 = p[e + 1][f + 1], P12 = p[e + 1][f + 2];
                        float P20 = p[e + 2][f], P21 = p[e + 2][f + 1], P22 = p[e + 2][f + 2];
                        acc[o][2 * e][2 * f]         += W4[15] * P00 + W4[13] * P01 + W4[7] * P10 + W4[5] * P11;
                        acc[o][2 * e][2 * f + 1]     += W4[14] * P01 + W4[12] * P02 + W4[6] * P11 + W4[4] * P12;
                        acc[o][2 * e + 1][2 * f]     += W4[11] * P10 + W4[9]  * P11 + W4[3] * P20 + W4[1] * P21;
                        acc[o][2 * e + 1][2 * f + 1] += W4[10] * P11 + W4[8]  * P12 + W4[2] * P21 + W4[0] * P22;
                    }
            }
        }
    }
#pragma unroll
    for (int o = 0; o < OCB; o++) {
        int oc = ob * OCB + o;
        float bv = bias[oc];
#pragma unroll
        for (int r = 0; r < 4; r++)
#pragma unroll
            for (int c = 0; c < 4; c += 2) {
                float v0 = fmaxf(acc[o][r][c] + bv, 0.f);
                float v1 = fmaxf(acc[o][r][c + 1] + bv, 0.f);
                *(float2*)(out + ((size_t)((size_t)b * OC + oc) * Ho + (Yo0 + 4 * ty + r)) * Ho
                               + Xo0 + 4 * tx + c) = make_float2(v0, v1);
            }
    }
}

// ====================================================================
// Host launcher — fork/join multi-stream
// ====================================================================
static cudaStream_t s_bg = nullptr, s_skip = nullptr;
static cudaEvent_t  e_root = nullptr, e_bgdone = nullptr, e_skipdone = nullptr;

extern "C" void kernel_launch(void* const* d_in, const int* in_sizes, int n_in,
                              void* d_out, int out_size)
{
    if (!s_bg) {
        cudaStreamCreateWithFlags(&s_bg,   cudaStreamNonBlocking);
        cudaStreamCreateWithFlags(&s_skip, cudaStreamNonBlocking);
        cudaEventCreateWithFlags(&e_root,     cudaEventDisableTiming);
        cudaEventCreateWithFlags(&e_bgdone,   cudaEventDisableTiming);
        cudaEventCreateWithFlags(&e_skipdone, cudaEventDisableTiming);
    }
    const float* x        = (const float*)d_in[0];
    const float* ce_w1    = (const float*)d_in[1];
    const float* ce_b1    = (const float*)d_in[2];
    const float* ce_w2    = (const float*)d_in[3];
    const float* ce_b2    = (const float*)d_in[4];
    const float* se_w1    = (const float*)d_in[5];
    const float* se_b1    = (const float*)d_in[6];
    const float* se_w2    = (const float*)d_in[7];
    const float* se_b2    = (const float*)d_in[8];
    const float* mem_keys = (const float*)d_in[9];
    const float* mem_vals = (const float*)d_in[10];
    const float* mem_hard = (const float*)d_in[11];
    const float* dec_w1   = (const float*)d_in[12];
    const float* dec_b1   = (const float*)d_in[13];
    const float* dec_tw1  = (const float*)d_in[14];
    const float* dec_tb1  = (const float*)d_in[15];
    const float* dec_tw2  = (const float*)d_in[16];
    const float* dec_tb2  = (const float*)d_in[17];
    const float* dec_w2   = (const float*)d_in[18];
    const float* dec_b2   = (const float*)d_in[19];
    float* outp = (float*)d_out;

    float *knT, *hnT, *A, *A2, *zc, *zs, *Sact, *tw, *bgz, *c9, *gdelta, *zmS, *d1, *u1, *u2, *pv;
    int *tidx, *amax, *pi;
    cudaGetSymbolAddress((void**)&knT,    g_knT);
    cudaGetSymbolAddress((void**)&hnT,    g_hnT);
    cudaGetSymbolAddress((void**)&A,      g_A);
    cudaGetSymbolAddress((void**)&A2,     g_A2);
    cudaGetSymbolAddress((void**)&zc,     g_zc);
    cudaGetSymbolAddress((void**)&zs,     g_zs);
    cudaGetSymbolAddress((void**)&Sact,   g_Sact);
    cudaGetSymbolAddress((void**)&tidx,   g_tidx);
    cudaGetSymbolAddress((void**)&tw,     g_tw);
    cudaGetSymbolAddress((void**)&amax,   g_amax);
    cudaGetSymbolAddress((void**)&pv,     g_pv);
    cudaGetSymbolAddress((void**)&pi,     g_pi);
    cudaGetSymbolAddress((void**)&bgz,    g_bgz);
    cudaGetSymbolAddress((void**)&c9,     g_c9);
    cudaGetSymbolAddress((void**)&gdelta, g_gdelta);
    cudaGetSymbolAddress((void**)&zmS,    g_zmS);
    cudaGetSymbolAddress((void**)&d1,     g_d1);
    cudaGetSymbolAddress((void**)&u1,     g_u1);
    cudaGetSymbolAddress((void**)&u2,     g_u2);

    // root: normalized memory tables
    k_normrows<<<200, 256>>>(mem_keys, mem_hard, knT, hnT);
    cudaEventRecord(e_root, 0);

    // ---- bg branch: bgz then C9 table ----
    cudaStreamWaitEvent(s_bg, e_root, 0);
    k_bg<<<1, 256, 0, s_bg>>>(ce_w2, ce_b1, ce_b2, knT, mem_vals, bgz);
    k_prepC9<<<1, 256, 0, s_bg>>>(dec_w1, dec_b1, bgz, c9);
    cudaEventRecord(e_bgdone, s_bg);

    // ---- skip branch ----
    cudaStreamWaitEvent(s_skip, e_root, 0);
    k_enc1<16, false><<<dim3(8, 8, 16), 256, 0, s_skip>>>(x, se_w1, se_b1, A2, 0, 0);
    k_conv3c<4, true, true, false><<<dim3(2, 4 * 32, 16), 128, 0, s_skip>>>(
        A2, se_w2, se_b2, zs, 16, 16, 128, 128, 128, 4, 0, 0, nullptr);
    k_gemm_amax_split<<<dim3(7, 32, 16), 256, 0, s_skip>>>(zs, hnT, pv, pi);
    k_amax_reduce<<<256, 256, 0, s_skip>>>(pv, pi, amax);
    k_gatherS<<<8192, 256, 0, s_skip>>>(mem_hard, amax, zmS);
    cudaEventRecord(e_skipdone, s_skip);

    // ---- center branch (main stream) ----
    k_fillA<<<(16 * 32 * 16384) / 256, 256>>>(A, ce_b1);
    k_enc1<32, true><<<dim3(4, 4, 16), 256>>>(x, ce_w1, ce_b1, A, 2, 2);
    k_conv3c<4, true, true, false><<<dim3(1, 2 * 32, 16), 128>>>(
        A, ce_w2, ce_b2, zc, 32, 32, 128, 128, 128, 2, 32, 32, nullptr);
    k_gemm_act<<<dim3(13, 3, 16), 256>>>(zc, knT, Sact);
    k_topk_act<<<(16 * 324 + 7) / 8, 256>>>(Sact, zc, tidx, tw);
    cudaStreamWaitEvent(0, e_bgdone, 0);   // bgz + c9 ready
    k_gatherC_act<<<(16 * 324) / 8, 256>>>(mem_vals, tidx, tw, bgz, gdelta);

    // ---- join, decoder ----
    cudaStreamWaitEvent(0, e_skipdone, 0);
    // dec1 main: skip channels only (w offset 128 ic), + C9 background, raw output
    k_conv3c<2, false, false, true><<<dim3(1, 2 * 32, 16), 128>>>(
        zmS, dec_w1 + 128 * 9, dec_b1, d1, 128, 256, 64, 64, 64, 2, 0, 0, c9);
    k_dec1delta<<<dim3(4, 16), 256>>>(gdelta, dec_w1, d1);
    k_deconv<64, 32, 4, true><<<dim3(2, 2 * 8, 16), 256>>>(d1, dec_tw1, dec_tb1, u1, 64, 2);
    k_deconv<32, 16, 4, false><<<dim3(4, 4 * 4, 16), 256>>>(u1, dec_tw2, dec_tb2, u2, 128, 4);
    k_conv3c<1, false, false, false><<<dim3(4, 8, 16), 128>>>(
        u2, dec_w2, dec_b2, outp, 16, 16, 1, 256, 256, 8, 0, 0, nullptr);
}

// round 12
// speedup vs baseline: 1.0158x; 1.0158x over previous
#include <cuda_runtime.h>
#include <math.h>
#include <stdint.h>

// ====================================================================
// Static device scratch
// ====================================================================
__device__ __align__(256) float g_knT[128 * 800];
__device__ __align__(256) float g_hnT[128 * 800];
__device__ __align__(256) float g_A  [16 * 32 * 128 * 128];   // center enc1 out
__device__ __align__(256) float g_A2 [16 * 16 * 128 * 128];   // skip enc1 out
__device__ __align__(256) float g_zc [16 * 128 * 64 * 64];
__device__ __align__(256) float g_zs [16 * 128 * 64 * 64];
__device__ __align__(256) float g_Sact[16 * 384 * 800];
__device__ __align__(256) int   g_tidx[16 * 324 * 10];
__device__ __align__(256) float g_tw  [16 * 324 * 10];
__device__ __align__(256) int   g_amax[65536];
__device__ __align__(256) float g_bgz [128];
__device__ __align__(256) float g_c9  [64 * 9];
__device__ __align__(256) float g_gdelta[16 * 128 * 324];
__device__ __align__(256) float g_zmS[16 * 128 * 64 * 64];    // skip gather only
__device__ __align__(256) float g_d1 [16 * 64 * 64 * 64];     // raw (pre-relu)
__device__ __align__(256) float g_u1 [16 * 32 * 128 * 128];
__device__ __align__(256) float g_u2 [16 * 16 * 256 * 256];

// ====================================================================
// Normalize memory rows -> transposed tables knT[c][m], hnT[c][m]
// ====================================================================
__global__ void k_normrows(const float* __restrict__ keys,
                           const float* __restrict__ hard,
                           float* __restrict__ knT, float* __restrict__ hnT)
{
    int gw = (blockIdx.x * blockDim.x + threadIdx.x) >> 5;
    int lane = threadIdx.x & 31;
    if (gw >= 1600) return;
    const float* src; float* dst; int r;
    if (gw < 800) { src = keys; dst = knT; r = gw; }
    else          { src = hard; dst = hnT; r = gw - 800; }
    float4 v = *(const float4*)(src + (size_t)r * 128 + lane * 4);
    float s = v.x * v.x + v.y * v.y + v.z * v.z + v.w * v.w;
#pragma unroll
    for (int o = 16; o > 0; o >>= 1) s += __shfl_xor_sync(0xffffffffu, s, o);
    float d = 1.0f / fmaxf(sqrtf(s), 1e-12f);
    dst[(size_t)(4 * lane + 0) * 800 + r] = v.x * d;
    dst[(size_t)(4 * lane + 1) * 800 + r] = v.y * d;
    dst[(size_t)(4 * lane + 2) * 800 + r] = v.z * d;
    dst[(size_t)(4 * lane + 3) * 800 + r] = v.w * d;
}

// ====================================================================
// Background z_match: bgc -> scores -> topk -> softmax -> gather (1 block)
// ====================================================================
__global__ __launch_bounds__(256) void k_bg(const float* __restrict__ w2,
    const float* __restrict__ b1, const float* __restrict__ b2,
    const float* __restrict__ knT, const float* __restrict__ vals,
    float* __restrict__ bgz)
{
    __shared__ float bgc[128];
    __shared__ float sc[800];
    __shared__ int   swidx[10];
    __shared__ float sww[10];
    const int tid = threadIdx.x;
    if (tid < 128) {
        float s = b2[tid];
        for (int ic = 0; ic < 32; ic++) {
            float wsum = 0.f;
#pragma unroll
            for (int k = 0; k < 9; k++) wsum += w2[((size_t)tid * 32 + ic) * 9 + k];
            s = fmaf(wsum, fmaxf(b1[ic], 0.f), s);
        }
        bgc[tid] = fmaxf(s, 0.f);
    }
    __syncthreads();
    for (int m = tid; m < 800; m += 256) {
        float s = 0.f;
#pragma unroll 8
        for (int c = 0; c < 128; c++) s = fmaf(bgc[c], knT[(size_t)c * 800 + m], s);
        sc[m] = s;
    }
    __syncthreads();
    if (tid < 32) {
        const int lane = tid;
        float ss = 0.f;
#pragma unroll
        for (int j = 0; j < 4; j++) { float v = bgc[lane * 4 + j]; ss = fmaf(v, v, ss); }
#pragma unroll
        for (int o = 16; o > 0; o >>= 1) ss += __shfl_xor_sync(0xffffffffu, ss, o);
        float scale = 1.0f / fmaxf(sqrtf(ss), 1e-12f);
        float lv[10]; int li[10];
#pragma unroll
        for (int j = 0; j < 10; j++) { lv[j] = -INFINITY; li[j] = 0x7fffffff; }
        for (int t = 0; t < 25; t++) {
            int m = lane + 32 * t;
            float v = sc[m];
            int i = m;
#pragma unroll
            for (int j = 0; j < 10; j++) {
                bool better = (v > lv[j]) || (v == lv[j] && i < li[j]);
                if (better) {
                    float tv = lv[j]; lv[j] = v; v = tv;
                    int ti = li[j]; li[j] = i; i = ti;
                }
            }
        }
        float bv[10]; int bi[10];
#pragma unroll
        for (int k = 0; k < 10; k++) {
            float cv = lv[0]; int ci = li[0];
#pragma unroll
            for (int off = 16; off > 0; off >>= 1) {
                float ov = __shfl_xor_sync(0xffffffffu, cv, off);
                int   oi = __shfl_xor_sync(0xffffffffu, ci, off);
                if (ov > cv || (ov == cv && oi < ci)) { cv = ov; ci = oi; }
            }
            bv[k] = cv; bi[k] = ci;
            if (lv[0] == cv && li[0] == ci) {
#pragma unroll
                for (int j = 0; j < 9; j++) { lv[j] = lv[j + 1]; li[j] = li[j + 1]; }
                lv[9] = -INFINITY; li[9] = 0x7fffffff;
            }
        }
        if (lane == 0) {
            float mx = bv[0] * scale;
            float e[10], sum = 0.f;
#pragma unroll
            for (int k = 0; k < 10; k++) { e[k] = expf(bv[k] * scale - mx); sum += e[k]; }
            float inv = 1.0f / sum;
#pragma unroll
            for (int k = 0; k < 10; k++) { swidx[k] = bi[k]; sww[k] = e[k] * inv; }
        }
    }
    __syncthreads();
    if (tid < 128) {
        float a = 0.f;
#pragma unroll
        for (int k = 0; k < 10; k++)
            a = fmaf(vals[(size_t)swidx[k] * 128 + tid], sww[k], a);
        bgz[tid] = a;
    }
}

// ====================================================================
// C9 prep: c9[oc][cy][cx] = dec_b1[oc] + sum_ic<128 bgz[ic]*sum_{valid taps} w1
// ====================================================================
__global__ void k_prepC9(const float* __restrict__ w, const float* __restrict__ bias,
                         const float* __restrict__ bgz, float* __restrict__ c9)
{
    for (int idx = threadIdx.x; idx < 576; idx += 256) {
        int oc = idx / 9, cs = idx % 9, cy = cs / 3, cx = cs % 3;
        int dy0 = (cy == 0) ? 1 : 0, dy1 = (cy == 2) ? 1 : 2;
        int dx0 = (cx == 0) ? 1 : 0, dx1 = (cx == 2) ? 1 : 2;
        float s = bias[oc];
        for (int ic = 0; ic < 128; ic++) {
            float t = 0.f;
            const float* wp = w + ((size_t)oc * 256 + ic) * 9;
            for (int dy = dy0; dy <= dy1; dy++)
                for (int dx = dx0; dx <= dx1; dx++)
                    t += wp[dy * 3 + dx];
            s = fmaf(bgz[ic], t, s);
        }
        c9[idx] = s;
    }
}

// ====================================================================
// Fill A (enc1-center out) with relu(b1[c])
// ====================================================================
__global__ void k_fillA(float* __restrict__ A, const float* __restrict__ b1)
{
    int i = blockIdx.x * blockDim.x + threadIdx.x;   // < 16*32*16384
    int c = (i >> 14) & 31;
    A[i] = fmaxf(b1[c], 0.f);
}

// ====================================================================
// Encoder stage 1: conv3x3 (1 -> CO) + relu + maxpool2, tile offset.
// ====================================================================
template<int CO, bool MASK>
__global__ __launch_bounds__(256) void k_enc1(const float* __restrict__ x,
    const float* __restrict__ w, const float* __restrict__ bias,
    float* __restrict__ out, int offX, int offY)
{
    __shared__ float tile[34][36];
    __shared__ float sw[CO * 9];
    __shared__ float sb[CO];
    const int t  = threadIdx.x;
    const int b  = blockIdx.z;
    const int Y0 = (blockIdx.y + offY) * 32;
    const int X0 = (blockIdx.x + offX) * 32;
    const float* xb = x + (size_t)b * 65536;
    for (int i = t; i < 34 * 34; i += 256) {
        int r = i / 34, c = i % 34;
        int gy = Y0 + r - 1, gx = X0 + c - 1;
        bool ok = (gy >= 0 && gy < 256 && gx >= 0 && gx < 256);
        if (MASK) ok = ok && (gy >= 96 && gy < 160 && gx >= 96 && gx < 160);
        tile[r][c] = ok ? xb[gy * 256 + gx] : 0.f;
    }
    for (int i = t; i < CO * 9; i += 256) sw[i] = w[i];
    if (t < CO) sb[t] = bias[t];
    __syncthreads();
    const int ty = t >> 4, tx = t & 15;
    float p[4][4];
#pragma unroll
    for (int i = 0; i < 4; i++)
#pragma unroll
        for (int j = 0; j < 4; j++) p[i][j] = tile[2 * ty + i][2 * tx + j];
    const int py = (blockIdx.y + offY) * 16 + ty, px = (blockIdx.x + offX) * 16 + tx;
    float* ob = out + (size_t)b * CO * 128 * 128 + py * 128 + px;
#pragma unroll 4
    for (int oc = 0; oc < CO; oc++) {
        float w9[9];
#pragma unroll
        for (int k = 0; k < 9; k++) w9[k] = sw[oc * 9 + k];
        float bv = sb[oc];
        float m = -INFINITY;
#pragma unroll
        for (int i = 0; i < 2; i++)
#pragma unroll
            for (int j = 0; j < 2; j++) {
                float s = bv;
#pragma unroll
                for (int dy = 0; dy < 3; dy++)
#pragma unroll
                    for (int dx = 0; dx < 3; dx++)
                        s = fmaf(w9[dy * 3 + dx], p[i + dy][j + dx], s);
                m = fmaxf(m, fmaxf(s, 0.f));
            }
        ob[(size_t)oc * 128 * 128] = m;
    }
}

// ====================================================================
// conv3x3 pad1. 64(w) x 32(h) output tile, 128 threads, 4x4 px/thread.
// ICw = weight oc-stride; C9MODE adds c9[oc][case] (bias folded).
// ====================================================================
template<int OCB, bool RELU, bool POOL, bool C9MODE>
__global__ __launch_bounds__(128) void k_conv3c(const float* __restrict__ in,
    const float* __restrict__ w, const float* __restrict__ bias,
    float* __restrict__ out, int IC, int ICw, int OC, int H, int W, int tilesY,
    int offXpx, int offYpx, const float* __restrict__ c9)
{
    __shared__ float tin[4][34][66];
    __shared__ float sw[OCB][4][9];
    const int tY = blockIdx.y % tilesY;
    const int ob = blockIdx.y / tilesY;
    const int Y0 = tY * 32 + offYpx;
    const int X0 = blockIdx.x * 64 + offXpx;
    const int b  = blockIdx.z;
    const int tid = threadIdx.x;
    const int ty = tid >> 4;
    const int tx = tid & 15;
    float acc[OCB][4][4];
#pragma unroll
    for (int o = 0; o < OCB; o++)
#pragma unroll
        for (int e = 0; e < 4; e++)
#pragma unroll
            for (int f = 0; f < 4; f++) acc[o][e][f] = 0.f;
    const float* inb = in + (size_t)b * IC * H * W;
    for (int ic0 = 0; ic0 < IC; ic0 += 4) {
        __syncthreads();
        for (int i = tid; i < 4 * 34 * 66; i += 128) {
            int ic = i / (34 * 66); int rem = i % (34 * 66);
            int r = rem / 66, c = rem % 66;
            int gy = Y0 + r - 1, gx = X0 + c - 1;
            float v = 0.f;
            if (gy >= 0 && gy < H && gx >= 0 && gx < W)
                v = inb[(size_t)(ic0 + ic) * H * W + gy * W + gx];
            tin[ic][r][c] = v;
        }
        for (int i = tid; i < OCB * 4 * 9; i += 128) {
            int o = i / 36; int rem = i % 36; int ic = rem / 9; int k = rem % 9;
            sw[o][ic][k] = w[((size_t)(ob * OCB + o) * ICw + ic0 + ic) * 9 + k];
        }
        __syncthreads();
#pragma unroll
        for (int ic = 0; ic < 4; ic++) {
            float p[6][6];
#pragma unroll
            for (int i = 0; i < 6; i++)
#pragma unroll
                for (int j = 0; j < 6; j++)
                    p[i][j] = tin[ic][4 * ty + i][4 * tx + j];
#pragma unroll
            for (int o = 0; o < OCB; o++) {
                float w9[9];
#pragma unroll
                for (int k = 0; k < 9; k++) w9[k] = sw[o][ic][k];
#pragma unroll
                for (int e = 0; e < 4; e++)
#pragma unroll
                    for (int f = 0; f < 4; f++) {
                        float s = acc[o][e][f];
#pragma unroll
                        for (int dy = 0; dy < 3; dy++)
#pragma unroll
                            for (int dx = 0; dx < 3; dx++)
                                s = fmaf(w9[dy * 3 + dx], p[e + dy][f + dx], s);
                        acc[o][e][f] = s;
                    }
            }
        }
    }
#pragma unroll
    for (int o = 0; o < OCB; o++) {
        int oc = ob * OCB + o;
        if (C9MODE) {
#pragma unroll
            for (int e = 0; e < 4; e++) {
                int gy = Y0 + 4 * ty + e;
                int cyi = (gy == 0) ? 0 : ((gy == H - 1) ? 6 : 3);
                float vv[4];
#pragma unroll
                for (int f = 0; f < 4; f++) {
                    int gx = X0 + 4 * tx + f;
                    int cxi = (gx == 0) ? 0 : ((gx == W - 1) ? 2 : 1);
                    vv[f] = acc[o][e][f] + c9[oc * 9 + cyi + cxi];
                }
                *(float4*)(out + ((size_t)((size_t)b * OC + oc) * H + gy) * W
                               + X0 + 4 * tx) = make_float4(vv[0], vv[1], vv[2], vv[3]);
            }
        } else {
            float bv = bias[oc];
            if (POOL) {
                int Ho = H >> 1, Wo = W >> 1;
#pragma unroll
                for (int e = 0; e < 2; e++)
#pragma unroll
                    for (int f = 0; f < 2; f++) {
                        float m = -INFINITY;
#pragma unroll
                        for (int r = 0; r < 2; r++)
#pragma unroll
                            for (int c = 0; c < 2; c++)
                                m = fmaxf(m, fmaxf(acc[o][2 * e + r][2 * f + c] + bv, 0.f));
                        out[((size_t)((size_t)b * OC + oc) * Ho + ((Y0 >> 1) + 2 * ty + e)) * Wo
                            + (X0 >> 1) + 2 * tx + f] = m;
                    }
            } else {
#pragma unroll
                for (int e = 0; e < 4; e++) {
                    float v0 = acc[o][e][0] + bv, v1 = acc[o][e][1] + bv;
                    float v2 = acc[o][e][2] + bv, v3 = acc[o][e][3] + bv;
                    if (RELU) {
                        v0 = fmaxf(v0, 0.f); v1 = fmaxf(v1, 0.f);
                        v2 = fmaxf(v2, 0.f); v3 = fmaxf(v3, 0.f);
                    }
                    *(float4*)(out + ((size_t)((size_t)b * OC + oc) * H + (Y0 + 4 * ty + e)) * W
                                   + X0 + 4 * tx) = make_float4(v0, v1, v2, v3);
                }
            }
        }
    }
}

// ====================================================================
// Delta conv for dec1: d1[b][oc][y][x] += conv(gdelta) on window [22,42)^2
// ====================================================================
__global__ __launch_bounds__(256) void k_dec1delta(
    const float* __restrict__ gdelta, const float* __restrict__ w,
    float* __restrict__ d1)
{
    __shared__ float sd[16][324];
    __shared__ float sw[16][16][9];
    const int b  = blockIdx.y;
    const int og = blockIdx.x;
    const int tid = threadIdx.x;
    float acc[2][16];
#pragma unroll
    for (int pp = 0; pp < 2; pp++)
#pragma unroll
        for (int o = 0; o < 16; o++) acc[pp][o] = 0.f;
    for (int ic0 = 0; ic0 < 128; ic0 += 16) {
        __syncthreads();
        for (int i = tid; i < 16 * 324; i += 256)
            sd[i / 324][i % 324] = gdelta[((size_t)b * 128 + ic0 + i / 324) * 324 + i % 324];
        for (int i = tid; i < 16 * 16 * 9; i += 256) {
            int o = i / 144, r = i % 144, ic = r / 9, k = r % 9;
            sw[o][ic][k] = w[((size_t)(og * 16 + o) * 256 + ic0 + ic) * 9 + k];
        }
        __syncthreads();
#pragma unroll
        for (int pp = 0; pp < 2; pp++) {
            int p = pp * 256 + tid;
            if (p >= 400) continue;
            int y = 22 + p / 20, x = 22 + p % 20;
            for (int ic = 0; ic < 16; ic++) {
                float pv[9];
#pragma unroll
                for (int dy = 0; dy < 3; dy++)
#pragma unroll
                    for (int dx = 0; dx < 3; dx++) {
                        int r = y - 24 + dy, c = x - 24 + dx;
                        pv[dy * 3 + dx] = (r >= 0 && r < 18 && c >= 0 && c < 18)
                            ? sd[ic][r * 18 + c] : 0.f;
                    }
#pragma unroll
                for (int o = 0; o < 16; o++) {
                    float s = acc[pp][o];
#pragma unroll
                    for (int k = 0; k < 9; k++) s = fmaf(sw[o][ic][k], pv[k], s);
                    acc[pp][o] = s;
                }
            }
        }
    }
#pragma unroll
    for (int pp = 0; pp < 2; pp++) {
        int p = pp * 256 + tid;
        if (p >= 400) continue;
        int y = 22 + p / 20, x = 22 + p % 20;
#pragma unroll
        for (int o = 0; o < 16; o++) {
            size_t idx = ((size_t)b * 64 + og * 16 + o) * 4096 + y * 64 + x;
            d1[idx] += acc[pp][o];
        }
    }
}

// ====================================================================
// Center active GEMM: S_act[b*384+ai][m] = sum_c zc[b][c][n(ai)]*knT[c][m]
// ====================================================================
__global__ __launch_bounds__(256) void k_gemm_act(const float* __restrict__ A,
    const float* __restrict__ Bm, float* __restrict__ S)
{
    __shared__ float As[16][128];
    __shared__ float Bs[16][64];
    __shared__ int   map[128];
    const int b  = blockIdx.z;
    const int n0 = blockIdx.y * 128;
    const int m0 = blockIdx.x * 64;
    const int tid = threadIdx.x;
    const int tm = tid & 15, tn = tid >> 4;
    if (tid < 128) {
        int ai = n0 + tid;
        map[tid] = (ai < 324) ? ((23 + ai / 18) * 64 + 23 + ai % 18) : (23 * 64 + 23);
    }
    float acc[8][4];
#pragma unroll
    for (int i = 0; i < 8; i++)
#pragma unroll
        for (int j = 0; j < 4; j++) acc[i][j] = 0.f;
    const float* Ab = A + (size_t)b * 128 * 4096;
    const int lkB = tid >> 4, lmB = (tid * 4) & 63;
    __syncthreads();
    for (int k0 = 0; k0 < 128; k0 += 16) {
        __syncthreads();
#pragma unroll
        for (int j = 0; j < 8; j++) {
            int idx = tid * 8 + j;
            int lk = idx >> 7, ln = idx & 127;
            As[lk][ln] = Ab[(size_t)(k0 + lk) * 4096 + map[ln]];
        }
        float4 bv = make_float4(0.f, 0.f, 0.f, 0.f);
        if (m0 + lmB < 800)
            bv = *(const float4*)&Bm[(size_t)(k0 + lkB) * 800 + m0 + lmB];
        *(float4*)&Bs[lkB][lmB] = bv;
        __syncthreads();
#pragma unroll
        for (int k = 0; k < 16; k++) {
            float4 a0 = *(float4*)&As[k][tn * 8];
            float4 a1 = *(float4*)&As[k][tn * 8 + 4];
            float4 bb = *(float4*)&Bs[k][tm * 4];
            float av[8] = {a0.x, a0.y, a0.z, a0.w, a1.x, a1.y, a1.z, a1.w};
#pragma unroll
            for (int i = 0; i < 8; i++) {
                acc[i][0] = fmaf(av[i], bb.x, acc[i][0]);
                acc[i][1] = fmaf(av[i], bb.y, acc[i][1]);
                acc[i][2] = fmaf(av[i], bb.z, acc[i][2]);
                acc[i][3] = fmaf(av[i], bb.w, acc[i][3]);
            }
        }
    }
    const int m = m0 + tm * 4;
    if (m < 800) {
#pragma unroll
        for (int i = 0; i < 8; i++) {
            size_t row = (size_t)b * 384 + n0 + tn * 8 + i;
            *(float4*)&S[row * 800 + m] =
                make_float4(acc[i][0], acc[i][1], acc[i][2], acc[i][3]);
        }
    }
}

// ====================================================================
// Active top-10 + softmax (scale inline from zc). 5184 warps.
// ====================================================================
__global__ void k_topk_act(const float* __restrict__ S, const float* __restrict__ zc,
                           int* __restrict__ tidx, float* __restrict__ tw)
{
    int gw = (blockIdx.x * blockDim.x + threadIdx.x) >> 5;
    int lane = threadIdx.x & 31;
    if (gw >= 16 * 324) return;
    const int b = gw / 324, ai = gw % 324;
    const int n = (23 + ai / 18) * 64 + 23 + ai % 18;
    const float* zb = zc + (size_t)b * 128 * 4096 + n;
    float ss = 0.f;
#pragma unroll
    for (int j = 0; j < 4; j++) {
        float v = zb[(size_t)(lane + 32 * j) * 4096];
        ss = fmaf(v, v, ss);
    }
#pragma unroll
    for (int o = 16; o > 0; o >>= 1) ss += __shfl_xor_sync(0xffffffffu, ss, o);
    float sc = 1.0f / fmaxf(sqrtf(ss), 1e-12f);

    const float* row = S + ((size_t)b * 384 + ai) * 800;
    float lv[10]; int li[10];
#pragma unroll
    for (int j = 0; j < 10; j++) { lv[j] = -INFINITY; li[j] = 0x7fffffff; }
    for (int t = 0; t < 25; t++) {
        int m = lane + 32 * t;
        float v = row[m];
        int i = m;
#pragma unroll
        for (int j = 0; j < 10; j++) {
            bool better = (v > lv[j]) || (v == lv[j] && i < li[j]);
            if (better) {
                float tv = lv[j]; lv[j] = v; v = tv;
                int ti = li[j]; li[j] = i; i = ti;
            }
        }
    }
    float bv[10]; int bi[10];
#pragma unroll
    for (int k = 0; k < 10; k++) {
        float cv = lv[0]; int ci = li[0];
#pragma unroll
        for (int off = 16; off > 0; off >>= 1) {
            float ov = __shfl_xor_sync(0xffffffffu, cv, off);
            int   oi = __shfl_xor_sync(0xffffffffu, ci, off);
            if (ov > cv || (ov == cv && oi < ci)) { cv = ov; ci = oi; }
        }
        bv[k] = cv; bi[k] = ci;
        if (lv[0] == cv && li[0] == ci) {
#pragma unroll
            for (int j = 0; j < 9; j++) { lv[j] = lv[j + 1]; li[j] = li[j + 1]; }
            lv[9] = -INFINITY; li[9] = 0x7fffffff;
        }
    }
    if (lane == 0) {
        float mx = bv[0] * sc;
        float e[10], sum = 0.f;
#pragma unroll
        for (int k = 0; k < 10; k++) { e[k] = expf(bv[k] * sc - mx); sum += e[k]; }
        float inv = 1.0f / sum;
#pragma unroll
        for (int k = 0; k < 10; k++) {
            tidx[gw * 10 + k] = bi[k];
            tw[gw * 10 + k]   = e[k] * inv;
        }
    }
}

// ====================================================================
// Active weighted gather -> gdelta[b][c][ai] = z_match - bgz[c]
// ====================================================================
__global__ void k_gatherC_act(const float* __restrict__ vals, const int* __restrict__ tidx,
                              const float* __restrict__ tw, const float* __restrict__ bgz,
                              float* __restrict__ gdelta)
{
    __shared__ int   sidx[8][10];
    __shared__ float swt [8][10];
    const int r0 = blockIdx.x * 8;
    const int tid = threadIdx.x;
    if (tid < 80) {
        int ny = tid / 10, k = tid % 10;
        sidx[ny][k] = tidx[(size_t)(r0 + ny) * 10 + k];
        swt [ny][k] = tw  [(size_t)(r0 + ny) * 10 + k];
    }
    __syncthreads();
    const int cx = tid & 31, ny = tid >> 5;
    const int row = r0 + ny;
    const int b = row / 324, ai = row % 324;
#pragma unroll
    for (int cc = 0; cc < 4; cc++) {
        int c = cx + 32 * cc;
        float acc = 0.f;
#pragma unroll
        for (int k = 0; k < 10; k++)
            acc = fmaf(vals[(size_t)sidx[ny][k] * 128 + c], swt[ny][k], acc);
        gdelta[((size_t)b * 128 + c) * 324 + ai] = acc - bgz[c];
    }
}

// ====================================================================
// Skip GEMM + fused argmax. Tile 128n, m chunks of 128, 8x8 micro.
// ====================================================================
__global__ __launch_bounds__(256) void k_gemm_amax(const float* __restrict__ A,
    const float* __restrict__ Bm, int* __restrict__ amax)
{
    __shared__ float As[16][128];
    __shared__ float Bs[16][128];
    __shared__ float rv[128][17];
    __shared__ int   ri[128][17];
    const int b  = blockIdx.y;
    const int n0 = blockIdx.x * 128;
    const int tid = threadIdx.x;
    const int tm = tid & 15, tn = tid >> 4;
    const int lk = tid >> 4, ln = (tid & 15) * 8;
    const float* Ab = A + (size_t)b * 128 * 4096;
    float bestv[8]; int besti[8];
#pragma unroll
    for (int i = 0; i < 8; i++) { bestv[i] = -INFINITY; besti[i] = 0x7fffffff; }
    for (int m0 = 0; m0 < 800; m0 += 128) {
        float acc[8][8];
#pragma unroll
        for (int i = 0; i < 8; i++)
#pragma unroll
            for (int j = 0; j < 8; j++) acc[i][j] = 0.f;
        for (int k0 = 0; k0 < 128; k0 += 16) {
            __syncthreads();
            const float* ap = &Ab[(size_t)(k0 + lk) * 4096 + n0 + ln];
            *(float4*)&As[lk][ln]     = *(const float4*)ap;
            *(float4*)&As[lk][ln + 4] = *(const float4*)(ap + 4);
            if (m0 + ln + 7 < 800) {
                const float* bp = &Bm[(size_t)(k0 + lk) * 800 + m0 + ln];
                *(float4*)&Bs[lk][ln]     = *(const float4*)bp;
                *(float4*)&Bs[lk][ln + 4] = *(const float4*)(bp + 4);
            } else {
#pragma unroll
                for (int j = 0; j < 8; j++)
                    Bs[lk][ln + j] = (m0 + ln + j < 800)
                        ? Bm[(size_t)(k0 + lk) * 800 + m0 + ln + j] : 0.f;
            }
            __syncthreads();
#pragma unroll
            for (int k = 0; k < 16; k++) {
                float4 a0 = *(float4*)&As[k][tn * 8];
                float4 a1 = *(float4*)&As[k][tn * 8 + 4];
                float4 b0 = *(float4*)&Bs[k][tm * 8];
                float4 b1 = *(float4*)&Bs[k][tm * 8 + 4];
                float av[8] = {a0.x, a0.y, a0.z, a0.w, a1.x, a1.y, a1.z, a1.w};
                float bw[8] = {b0.x, b0.y, b0.z, b0.w, b1.x, b1.y, b1.z, b1.w};
#pragma unroll
                for (int i = 0; i < 8; i++)
#pragma unroll
                    for (int j = 0; j < 8; j++)
                        acc[i][j] = fmaf(av[i], bw[j], acc[i][j]);
            }
        }
#pragma unroll
        for (int i = 0; i < 8; i++)
#pragma unroll
            for (int j = 0; j < 8; j++) {
                int m = m0 + tm * 8 + j;
                float v = acc[i][j];
                if (m < 800 && (v > bestv[i] || (v == bestv[i] && m < besti[i]))) {
                    bestv[i] = v; besti[i] = m;
                }
            }
    }
    __syncthreads();
#pragma unroll
    for (int i = 0; i < 8; i++) { rv[tn * 8 + i][tm] = bestv[i]; ri[tn * 8 + i][tm] = besti[i]; }
    __syncthreads();
    if (tid < 128) {
        float bv = -INFINITY; int bi = 0x7fffffff;
#pragma unroll
        for (int t = 0; t < 16; t++) {
            float v = rv[tid][t]; int i = ri[tid][t];
            if (v > bv || (v == bv && i < bi)) { bv = v; bi = i; }
        }
        amax[b * 4096 + n0 + tid] = bi;
    }
}

// ====================================================================
// Hard gather -> zmS[b][c][n] (128-channel layout)
// ====================================================================
__global__ void k_gatherS(const float* __restrict__ hard, const int* __restrict__ amax,
                          float* __restrict__ zmS)
{
    const int r0 = blockIdx.x * 8;
    const int tid = threadIdx.x;
    const int cx = tid & 31, ny = tid >> 5;
    const int row = r0 + ny;
    const int b = row >> 12, n = row & 4095;
    const int a = amax[row];
#pragma unroll
    for (int cc = 0; cc < 4; cc++) {
        int c = cx + 32 * cc;
        zmS[((size_t)b * 128 + c) * 4096 + n] = hard[(size_t)a * 128 + c];
    }
}

// ====================================================================
// Transposed conv (k=4, s=2) + relu out; RELUIN applies relu on input load.
// IC chunks of 4 (halved barrier count).
// ====================================================================
template<int IC, int OC, int OCB, bool RELUIN>
__global__ __launch_bounds__(256) void k_deconv(const float* __restrict__ in,
    const float* __restrict__ w, const float* __restrict__ bias,
    float* __restrict__ out, int Hi, int tilesY)
{
    __shared__ float tin[4][34][36];
    __shared__ float sw[4][OCB][16];
    const int Ho = 2 * Hi;
    const int tY = blockIdx.y % tilesY;
    const int ob = blockIdx.y / tilesY;
    const int b  = blockIdx.z;
    const int Xo0 = blockIdx.x * 64, Yo0 = tY * 64;
    const int a0 = Yo0 >> 1, c0 = Xo0 >> 1;
    const int tid = threadIdx.x;
    const int ty = tid >> 4, tx = tid & 15;
    float acc[OCB][4][4];
#pragma unroll
    for (int o = 0; o < OCB; o++)
#pragma unroll
        for (int r = 0; r < 4; r++)
#pragma unroll
            for (int c = 0; c < 4; c++) acc[o][r][c] = 0.f;
    const float* inb = in + (size_t)b * IC * Hi * Hi;
    for (int ic0 = 0; ic0 < IC; ic0 += 4) {
        __syncthreads();
        for (int i = tid; i < 4 * 34 * 34; i += 256) {
            int ic = i / (34 * 34); int rem = i % (34 * 34);
            int r = rem / 34, c = rem % 34;
            int gy = a0 + r - 1, gx = c0 + c - 1;
            float v = 0.f;
            if (gy >= 0 && gy < Hi && gx >= 0 && gx < Hi) {
                v = inb[(size_t)(ic0 + ic) * Hi * Hi + gy * Hi + gx];
                if (RELUIN) v = fmaxf(v, 0.f);
            }
            tin[ic][r][c] = v;
        }
        for (int i = tid; i < 4 * OCB * 16; i += 256) {
            int ic = i / (OCB * 16); int rem = i % (OCB * 16);
            int o = rem / 16; int t = rem % 16;
            sw[ic][o][t] = w[((size_t)(ic0 + ic) * OC + ob * OCB + o) * 16 + t];
        }
        __syncthreads();
#pragma unroll
        for (int ic = 0; ic < 4; ic++) {
            float p[4][4];
#pragma unroll
            for (int i = 0; i < 4; i++)
#pragma unroll
                for (int j = 0; j < 4; j++)
                    p[i][j] = tin[ic][2 * ty + i][2 * tx + j];
#pragma unroll
            for (int o = 0; o < OCB; o++) {
                float W4[16];
#pragma unroll
                for (int t = 0; t < 16; t++) W4[t] = sw[ic][o][t];
#pragma unroll
                for (int e = 0; e < 2; e++)
#pragma unroll
                    for (int f = 0; f < 2; f++) {
                        float P00 = p[e][f],     P01 = p[e][f + 1],     P02 = p[e][f + 2];
                        float P10 = p[e + 1][f], P11 = p[e + 1][f + 1], P12 = p[e + 1][f + 2];
                        float P20 = p[e + 2][f], P21 = p[e + 2][f + 1], P22 = p[e + 2][f + 2];
                        acc[o][2 * e][2 * f]         += W4[15] * P00 + W4[13] * P01 + W4[7] * P10 + W4[5] * P11;
                        acc[o][2 * e][2 * f + 1]     += W4[14] * P01 + W4[12] * P02 + W4[6] * P11 + W4[4] * P12;
                        acc[o][2 * e + 1][2 * f]     += W4[11] * P10 + W4[9]  * P11 + W4[3] * P20 + W4[1] * P21;
                        acc[o][2 * e + 1][2 * f + 1] += W4[10] * P11 + W4[8]  * P12 + W4[2] * P21 + W4[0] * P22;
                    }
            }
        }
    }
#pragma unroll
    for (int o = 0; o < OCB; o++) {
        int oc = ob * OCB + o;
        float bv = bias[oc];
#pragma unroll
        for (int r = 0; r < 4; r++)
#pragma unroll
            for (int c = 0; c < 4; c += 2) {
                float v0 = fmaxf(acc[o][r][c] + bv, 0.f);
                float v1 = fmaxf(acc[o][r][c + 1] + bv, 0.f);
                *(float2*)(out + ((size_t)((size_t)b * OC + oc) * Ho + (Yo0 + 4 * ty + r)) * Ho
                               + Xo0 + 4 * tx + c) = make_float2(v0, v1);
            }
    }
}

// ====================================================================
// Host launcher — fork/join multi-stream; dec1-main moved to skip stream
// ====================================================================
static cudaStream_t s_bg = nullptr, s_skip = nullptr;
static cudaEvent_t  e_root = nullptr, e_bgdone = nullptr, e_skipdone = nullptr;

extern "C" void kernel_launch(void* const* d_in, const int* in_sizes, int n_in,
                              void* d_out, int out_size)
{
    if (!s_bg) {
        cudaStreamCreateWithFlags(&s_bg,   cudaStreamNonBlocking);
        cudaStreamCreateWithFlags(&s_skip, cudaStreamNonBlocking);
        cudaEventCreateWithFlags(&e_root,     cudaEventDisableTiming);
        cudaEventCreateWithFlags(&e_bgdone,   cudaEventDisableTiming);
        cudaEventCreateWithFlags(&e_skipdone, cudaEventDisableTiming);
    }
    const float* x        = (const float*)d_in[0];
    const float* ce_w1    = (const float*)d_in[1];
    const float* ce_b1    = (const float*)d_in[2];
    const float* ce_w2    = (const float*)d_in[3];
    const float* ce_b2    = (const float*)d_in[4];
    const float* se_w1    = (const float*)d_in[5];
    const float* se_b1    = (const float*)d_in[6];
    const float* se_w2    = (const float*)d_in[7];
    const float* se_b2    = (const float*)d_in[8];
    const float* mem_keys = (const float*)d_in[9];
    const float* mem_vals = (const float*)d_in[10];
    const float* mem_hard = (const float*)d_in[11];
    const float* dec_w1   = (const float*)d_in[12];
    const float* dec_b1   = (const float*)d_in[13];
    const float* dec_tw1  = (const float*)d_in[14];
    const float* dec_tb1  = (const float*)d_in[15];
    const float* dec_tw2  = (const float*)d_in[16];
    const float* dec_tb2  = (const float*)d_in[17];
    const float* dec_w2   = (const float*)d_in[18];
    const float* dec_b2   = (const float*)d_in[19];
    float* outp = (float*)d_out;

    float *knT, *hnT, *A, *A2, *zc, *zs, *Sact, *tw, *bgz, *c9, *gdelta, *zmS, *d1, *u1, *u2;
    int *tidx, *amax;
    cudaGetSymbolAddress((void**)&knT,    g_knT);
    cudaGetSymbolAddress((void**)&hnT,    g_hnT);
    cudaGetSymbolAddress((void**)&A,      g_A);
    cudaGetSymbolAddress((void**)&A2,     g_A2);
    cudaGetSymbolAddress((void**)&zc,     g_zc);
    cudaGetSymbolAddress((void**)&zs,     g_zs);
    cudaGetSymbolAddress((void**)&Sact,   g_Sact);
    cudaGetSymbolAddress((void**)&tidx,   g_tidx);
    cudaGetSymbolAddress((void**)&tw,     g_tw);
    cudaGetSymbolAddress((void**)&amax,   g_amax);
    cudaGetSymbolAddress((void**)&bgz,    g_bgz);
    cudaGetSymbolAddress((void**)&c9,     g_c9);
    cudaGetSymbolAddress((void**)&gdelta, g_gdelta);
    cudaGetSymbolAddress((void**)&zmS,    g_zmS);
    cudaGetSymbolAddress((void**)&d1,     g_d1);
    cudaGetSymbolAddress((void**)&u1,     g_u1);
    cudaGetSymbolAddress((void**)&u2,     g_u2);

    // root: normalized memory tables
    k_normrows<<<200, 256>>>(mem_keys, mem_hard, knT, hnT);
    cudaEventRecord(e_root, 0);

    // ---- bg branch: bgz then C9 table ----
    cudaStreamWaitEvent(s_bg, e_root, 0);
    k_bg<<<1, 256, 0, s_bg>>>(ce_w2, ce_b1, ce_b2, knT, mem_vals, bgz);
    k_prepC9<<<1, 256, 0, s_bg>>>(dec_w1, dec_b1, bgz, c9);
    cudaEventRecord(e_bgdone, s_bg);

    // ---- skip branch: encoder + matching + dec1-main (needs only zmS + c9) ----
    cudaStreamWaitEvent(s_skip, e_root, 0);
    k_enc1<16, false><<<dim3(8, 8, 16), 256, 0, s_skip>>>(x, se_w1, se_b1, A2, 0, 0);
    k_conv3c<4, true, true, false><<<dim3(2, 4 * 32, 16), 128, 0, s_skip>>>(
        A2, se_w2, se_b2, zs, 16, 16, 128, 128, 128, 4, 0, 0, nullptr);
    k_gemm_amax<<<dim3(32, 16), 256, 0, s_skip>>>(zs, hnT, amax);
    k_gatherS<<<8192, 256, 0, s_skip>>>(mem_hard, amax, zmS);
    cudaStreamWaitEvent(s_skip, e_bgdone, 0);       // c9 ready
    k_conv3c<4, false, false, true><<<dim3(1, 2 * 16, 16), 128, 0, s_skip>>>(
        zmS, dec_w1 + 128 * 9, dec_b1, d1, 128, 256, 64, 64, 64, 2, 0, 0, c9);
    cudaEventRecord(e_skipdone, s_skip);

    // ---- center branch (main stream), overlaps with skip + dec1-main ----
    k_fillA<<<(16 * 32 * 16384) / 256, 256>>>(A, ce_b1);
    k_enc1<32, true><<<dim3(4, 4, 16), 256>>>(x, ce_w1, ce_b1, A, 2, 2);
    k_conv3c<4, true, true, false><<<dim3(1, 2 * 32, 16), 128>>>(
        A, ce_w2, ce_b2, zc, 32, 32, 128, 128, 128, 2, 32, 32, nullptr);
    k_gemm_act<<<dim3(13, 3, 16), 256>>>(zc, knT, Sact);
    k_topk_act<<<(16 * 324 + 7) / 8, 256>>>(Sact, zc, tidx, tw);
    cudaStreamWaitEvent(0, e_bgdone, 0);   // bgz ready
    k_gatherC_act<<<(16 * 324) / 8, 256>>>(mem_vals, tidx, tw, bgz, gdelta);

    // ---- join: delta add then deconvs ----
    cudaStreamWaitEvent(0, e_skipdone, 0);
    k_dec1delta<<<dim3(4, 16), 256>>>(gdelta, dec_w1, d1);
    k_deconv<64, 32, 4, true><<<dim3(2, 2 * 8, 16), 256>>>(d1, dec_tw1, dec_tb1, u1, 64, 2);
    k_deconv<32, 16, 4, false><<<dim3(4, 4 * 4, 16), 256>>>(u1, dec_tw2, dec_tb2, u2, 128, 4);
    k_conv3c<1, false, false, false><<<dim3(4, 8, 16), 128>>>(
        u2, dec_w2, dec_b2, outp, 16, 16, 1, 256, 256, 8, 0, 0, nullptr);
}